// round 1
// baseline (speedup 1.0000x reference)
#include <cuda_runtime.h>
#include <cuda_bf16.h>
#include <math.h>

// ---------------------------------------------------------------------------
// E8QLinear: wq = E8-lattice-quantize(weight, per-row norm scaling)
//            out = x @ wq.T + bias
// Shapes: x [B=4096, IN=4096], weight [OUT=4096, IN=4096], bias [OUT]
// ---------------------------------------------------------------------------

#define MAXN 4096
// Scratch for quantized weights (device-global: no allocations allowed).
__device__ float g_wq[(size_t)MAXN * (size_t)MAXN];

// ---------------------------------------------------------------------------
// E8 lattice quantization (matches JAX reference semantics)
// ---------------------------------------------------------------------------

// Nearest point in D8 (integer vectors with even coordinate sum).
// jnp.round == round-half-to-even == rintf (default rounding mode).
// argmax tie-break: first index (strict > keeps first).
__device__ __forceinline__ void nearest_d8(const float x[8], float out[8]) {
    float f[8], d[8];
    float fsum = 0.f;
#pragma unroll
    for (int i = 0; i < 8; ++i) {
        f[i] = rintf(x[i]);
        d[i] = x[i] - f[i];
        fsum += f[i];
    }
    long long s = llrintf(fsum);          // exact: sum of small integers
    bool even = ((s & 1LL) == 0LL);       // works for negatives too

    int idx = 0;
    float best = fabsf(d[0]);
#pragma unroll
    for (int i = 1; i < 8; ++i) {
        float a = fabsf(d[i]);
        if (a > best) { best = a; idx = i; }
    }
#pragma unroll
    for (int i = 0; i < 8; ++i) out[i] = f[i];
    if (!even) out[idx] += (d[idx] >= 0.f) ? 1.f : -1.f;
}

// Nearest point in E8 = D8 U (D8 + 1/2). Tie (d0 <= d1) -> y0.
__device__ __forceinline__ void e8_quantize(const float x[8], float y[8]) {
    float y0[8], y1[8], xs[8];
    nearest_d8(x, y0);
#pragma unroll
    for (int i = 0; i < 8; ++i) xs[i] = x[i] - 0.5f;
    nearest_d8(xs, y1);
#pragma unroll
    for (int i = 0; i < 8; ++i) y1[i] += 0.5f;

    float d0 = 0.f, d1 = 0.f;
#pragma unroll
    for (int i = 0; i < 8; ++i) {
        float a = x[i] - y0[i]; d0 += a * a;
        float b = x[i] - y1[i]; d1 += b * b;
    }
    bool pick0 = (d0 <= d1);
#pragma unroll
    for (int i = 0; i < 8; ++i) y[i] = pick0 ? y0[i] : y1[i];
}

// One block per weight row. Row norm -> scale -> E8 quantize -> rescale.
__global__ __launch_bounds__(256) void quant_kernel(
    const float* __restrict__ w, int IN, float sf)
{
    const int row = blockIdx.x;
    const float* wr = w + (size_t)row * IN;
    const float4* w4 = (const float4*)wr;
    const int n4 = IN >> 2;

    // --- row sum of squares ---
    float ss = 0.f;
    for (int i = threadIdx.x; i < n4; i += blockDim.x) {
        float4 v = w4[i];
        ss += v.x * v.x + v.y * v.y + v.z * v.z + v.w * v.w;
    }
    __shared__ float red[256];
    red[threadIdx.x] = ss;
    __syncthreads();
#pragma unroll
    for (int off = 128; off > 0; off >>= 1) {
        if (threadIdx.x < off) red[threadIdx.x] += red[threadIdx.x + off];
        __syncthreads();
    }
    __shared__ float s_rn;
    if (threadIdx.x == 0) s_rn = fmaxf(sqrtf(red[0]), 1e-8f);
    __syncthreads();
    const float rn = s_rn;

    // --- quantize 8-element blocks ---
    float* wqr = g_wq + (size_t)row * IN;
    const int nblk = IN >> 3;
    for (int b = threadIdx.x; b < nblk; b += blockDim.x) {
        float4 a = w4[b * 2 + 0];
        float4 c = w4[b * 2 + 1];
        float xin[8] = { a.x, a.y, a.z, a.w, c.x, c.y, c.z, c.w };
#pragma unroll
        for (int i = 0; i < 8; ++i) xin[i] = (xin[i] / rn) * sf;  // (w/rn)*sf
        float q[8];
        e8_quantize(xin, q);
        float4 o0, o1;
        o0.x = q[0] * rn / sf; o0.y = q[1] * rn / sf;
        o0.z = q[2] * rn / sf; o0.w = q[3] * rn / sf;
        o1.x = q[4] * rn / sf; o1.y = q[5] * rn / sf;
        o1.z = q[6] * rn / sf; o1.w = q[7] * rn / sf;
        ((float4*)wqr)[b * 2 + 0] = o0;
        ((float4*)wqr)[b * 2 + 1] = o1;
    }
}

// ---------------------------------------------------------------------------
// SGEMM (NT): C[M,N] = A[M,K] * B[N,K]^T + bias[N]
// A = x (row-major), B = g_wq (row-major, K contiguous). 128x128x16 tiles,
// 256 threads, 8x8 micro-tile per thread.
// ---------------------------------------------------------------------------
#define BM 128
#define BN 128
#define BK 16
#define TM 8
#define TN 8
#define PAD 4   // (BM+PAD)*4B = 528B, divisible by 16 -> float4 LDS stays aligned

__global__ __launch_bounds__(256) void sgemm_nt_bias(
    const float* __restrict__ A,
    const float* __restrict__ bias,
    float* __restrict__ C,
    int M, int N, int K)
{
    __shared__ float As[BK][BM + PAD];
    __shared__ float Bs[BK][BN + PAD];

    const int tid = threadIdx.x;
    const int tx = tid & 15;        // 0..15 -> N direction
    const int ty = tid >> 4;        // 0..15 -> M direction
    const int rowBase = blockIdx.y * BM;
    const int colBase = blockIdx.x * BN;
    const float* B = g_wq;

    float acc[TM][TN];
#pragma unroll
    for (int i = 0; i < TM; ++i)
#pragma unroll
        for (int j = 0; j < TN; ++j) acc[i][j] = 0.f;

    for (int k0 = 0; k0 < K; k0 += BK) {
        // load A tile [BM x BK] transposed into As[k][m]
#pragma unroll
        for (int i = 0; i < 2; ++i) {
            int idx = tid + 256 * i;       // 0..511
            int r  = idx >> 2;             // tile row 0..127
            int cf = idx & 3;              // float4 within the 16-wide k slab
            float4 v = *(const float4*)(A + (size_t)(rowBase + r) * K + k0 + cf * 4);
            As[cf * 4 + 0][r] = v.x;
            As[cf * 4 + 1][r] = v.y;
            As[cf * 4 + 2][r] = v.z;
            As[cf * 4 + 3][r] = v.w;
        }
        // load B tile [BN x BK] transposed into Bs[k][n]
#pragma unroll
        for (int i = 0; i < 2; ++i) {
            int idx = tid + 256 * i;
            int r  = idx >> 2;
            int cf = idx & 3;
            float4 v = *(const float4*)(B + (size_t)(colBase + r) * K + k0 + cf * 4);
            Bs[cf * 4 + 0][r] = v.x;
            Bs[cf * 4 + 1][r] = v.y;
            Bs[cf * 4 + 2][r] = v.z;
            Bs[cf * 4 + 3][r] = v.w;
        }
        __syncthreads();

#pragma unroll
        for (int k = 0; k < BK; ++k) {
            float af[TM], bf[TN];
            float4 a0 = *(const float4*)&As[k][ty * TM];
            float4 a1 = *(const float4*)&As[k][ty * TM + 4];
            float4 b0 = *(const float4*)&Bs[k][tx * TN];
            float4 b1 = *(const float4*)&Bs[k][tx * TN + 4];
            af[0] = a0.x; af[1] = a0.y; af[2] = a0.z; af[3] = a0.w;
            af[4] = a1.x; af[5] = a1.y; af[6] = a1.z; af[7] = a1.w;
            bf[0] = b0.x; bf[1] = b0.y; bf[2] = b0.z; bf[3] = b0.w;
            bf[4] = b1.x; bf[5] = b1.y; bf[6] = b1.z; bf[7] = b1.w;
#pragma unroll
            for (int i = 0; i < TM; ++i)
#pragma unroll
                for (int j = 0; j < TN; ++j)
                    acc[i][j] = fmaf(af[i], bf[j], acc[i][j]);
        }
        __syncthreads();
    }

    // epilogue: add bias, store
    const int cb = colBase + tx * TN;
    float4 bb0 = *(const float4*)(bias + cb);
    float4 bb1 = *(const float4*)(bias + cb + 4);
#pragma unroll
    for (int i = 0; i < TM; ++i) {
        const int r = rowBase + ty * TM + i;
        float4 o0, o1;
        o0.x = acc[i][0] + bb0.x; o0.y = acc[i][1] + bb0.y;
        o0.z = acc[i][2] + bb0.z; o0.w = acc[i][3] + bb0.w;
        o1.x = acc[i][4] + bb1.x; o1.y = acc[i][5] + bb1.y;
        o1.z = acc[i][6] + bb1.z; o1.w = acc[i][7] + bb1.w;
        *(float4*)(C + (size_t)r * N + cb)     = o0;
        *(float4*)(C + (size_t)r * N + cb + 4) = o1;
    }
}

// ---------------------------------------------------------------------------
// launch
// ---------------------------------------------------------------------------
extern "C" void kernel_launch(void* const* d_in, const int* in_sizes, int n_in,
                              void* d_out, int out_size)
{
    const float* x    = (const float*)d_in[0];
    const float* w    = (const float*)d_in[1];
    const float* bias = (const float*)d_in[2];
    float* out = (float*)d_out;

    const int OUT = in_sizes[2];
    const int IN  = in_sizes[1] / OUT;
    const int B   = in_sizes[0] / IN;

    // adaptive = min(2, max(0.5, n_rows/10000)); sf = 60 * adaptive
    float adaptive = (float)OUT / 10000.0f;
    if (adaptive < 0.5f) adaptive = 0.5f;
    if (adaptive > 2.0f) adaptive = 2.0f;
    const float sf = 60.0f * adaptive;

    quant_kernel<<<OUT, 256>>>(w, IN, sf);

    dim3 grid(OUT / BN, B / BM);
    sgemm_nt_bias<<<grid, 256>>>(x, bias, out, B, OUT, IN);
}

// round 11
// speedup vs baseline: 4.5604x; 4.5604x over previous
#include <cuda_runtime.h>
#include <cuda_bf16.h>
#include <math.h>
#include <stdint.h>

// ===========================================================================
// E8QLinear on GB300 (sm_103 plain target -> legacy mma.sync tensor cores)
//   wq = qi * (rn/(2*sf)),  qi = 2*E8(w_scaled)  (small ints, exact in bf16)
//   out = (xhi+xlo) @ qi^T * colscale + bias
//   Single GEMM, K=8192: A=[xhi|xlo], B column k wraps mod 4096 into qi.
// ===========================================================================

#define ND 4096
#define KTOT 8192
__device__ __nv_bfloat16 g_xc[(size_t)ND * KTOT];  // [M, 8192] = [xhi | xlo]
__device__ __nv_bfloat16 g_qi[(size_t)ND * ND];    // [N, 4096] 2*q integers
__device__ float         g_cs[ND];                 // rn/(2*sf)

// ---------------------------------------------------------------------------
// E8 lattice quantizer (bit-exact vs JAX; validated round 1)
// ---------------------------------------------------------------------------
__device__ __forceinline__ void nearest_d8(const float x[8], float out[8]) {
    float f[8], d[8], fsum = 0.f;
#pragma unroll
    for (int i = 0; i < 8; ++i) { f[i] = rintf(x[i]); d[i] = x[i] - f[i]; fsum += f[i]; }
    long long s = llrintf(fsum);
    bool even = ((s & 1LL) == 0LL);
    int idx = 0; float best = fabsf(d[0]);
#pragma unroll
    for (int i = 1; i < 8; ++i) { float a = fabsf(d[i]); if (a > best) { best = a; idx = i; } }
#pragma unroll
    for (int i = 0; i < 8; ++i) out[i] = f[i];
    if (!even) out[idx] += (d[idx] >= 0.f) ? 1.f : -1.f;
}
__device__ __forceinline__ void e8_quantize(const float x[8], float y[8]) {
    float y0[8], y1[8], xs[8];
    nearest_d8(x, y0);
#pragma unroll
    for (int i = 0; i < 8; ++i) xs[i] = x[i] - 0.5f;
    nearest_d8(xs, y1);
#pragma unroll
    for (int i = 0; i < 8; ++i) y1[i] += 0.5f;
    float d0 = 0.f, d1 = 0.f;
#pragma unroll
    for (int i = 0; i < 8; ++i) {
        float a = x[i] - y0[i]; d0 += a * a;
        float b = x[i] - y1[i]; d1 += b * b;
    }
    bool p0 = (d0 <= d1);
#pragma unroll
    for (int i = 0; i < 8; ++i) y[i] = p0 ? y0[i] : y1[i];
}

__global__ __launch_bounds__(256) void quant_kernel(const float* __restrict__ w, float sf)
{
    const int row = blockIdx.x;
    const float4* w4 = (const float4*)(w + (size_t)row * ND);
    float ss = 0.f;
    for (int i = threadIdx.x; i < ND / 4; i += 256) {
        float4 v = w4[i];
        ss += v.x * v.x + v.y * v.y + v.z * v.z + v.w * v.w;
    }
    __shared__ float red[256];
    red[threadIdx.x] = ss;
    __syncthreads();
#pragma unroll
    for (int off = 128; off > 0; off >>= 1) {
        if (threadIdx.x < off) red[threadIdx.x] += red[threadIdx.x + off];
        __syncthreads();
    }
    __shared__ float s_rn;
    if (threadIdx.x == 0) {
        s_rn = fmaxf(sqrtf(red[0]), 1e-8f);
        g_cs[row] = s_rn / (2.0f * sf);
    }
    __syncthreads();
    const float rn = s_rn;

    __nv_bfloat16* qr = g_qi + (size_t)row * ND;
    for (int b = threadIdx.x; b < ND / 8; b += 256) {
        float4 a = w4[b * 2 + 0], c = w4[b * 2 + 1];
        float xin[8] = { a.x, a.y, a.z, a.w, c.x, c.y, c.z, c.w };
#pragma unroll
        for (int i = 0; i < 8; ++i) xin[i] = (xin[i] / rn) * sf;
        float q[8];
        e8_quantize(xin, q);
        __nv_bfloat16 o[8];
#pragma unroll
        for (int i = 0; i < 8; ++i) o[i] = __float2bfloat16(2.0f * q[i]);  // exact int
        *(uint4*)(qr + b * 8) = *(uint4*)o;
    }
}

// x -> [xhi | xlo] concatenated along K
__global__ __launch_bounds__(256) void split_kernel(const float* __restrict__ x)
{
    size_t flat = ((size_t)blockIdx.x * 256 + threadIdx.x) * 8;
    int m = (int)(flat >> 12);           // /4096
    int c = (int)(flat & 4095);
    float4 a = *(const float4*)(x + flat);
    float4 b = *(const float4*)(x + flat + 4);
    float v[8] = { a.x, a.y, a.z, a.w, b.x, b.y, b.z, b.w };
    __nv_bfloat16 hi[8], lo[8];
#pragma unroll
    for (int j = 0; j < 8; ++j) {
        hi[j] = __float2bfloat16(v[j]);
        lo[j] = __float2bfloat16(v[j] - __bfloat162float(hi[j]));
    }
    __nv_bfloat16* rowp = g_xc + (size_t)m * KTOT;
    *(uint4*)(rowp + c)        = *(uint4*)hi;
    *(uint4*)(rowp + ND + c)   = *(uint4*)lo;
}

// ---------------------------------------------------------------------------
// GEMM: C[4096,4096] = A[4096,8192] @ B[4096,4096(k wraps)]^T, * cs + bias
// BM=BN=128, BK=64 bf16 (128B rows, SW128), 3-stage cp.async, 8 warps (2x4),
// warp tile 64x32, mma.sync m16n8k16 bf16 -> fp32.
// ---------------------------------------------------------------------------
#define BM 128
#define BN 128
#define BK 64
#define STAGES 3
#define ASIZE (BM * 128)            // 16KB
#define BSIZE (BN * 128)            // 16KB
#define STAGE_BYTES (ASIZE + BSIZE) // 32KB
#define SMEM_TOTAL (STAGES * STAGE_BYTES)
#define NIT (KTOT / BK)             // 128

__device__ __forceinline__ uint32_t sw128(uint32_t b) { return b ^ ((b >> 3) & 0x70); }

__device__ __forceinline__ void ldsm_x4(uint32_t& r0, uint32_t& r1, uint32_t& r2,
                                        uint32_t& r3, uint32_t addr) {
    asm volatile("ldmatrix.sync.aligned.m8n8.x4.shared.b16 {%0,%1,%2,%3}, [%4];"
                 : "=r"(r0), "=r"(r1), "=r"(r2), "=r"(r3) : "r"(addr));
}
__device__ __forceinline__ void mma16816(float& c0, float& c1, float& c2, float& c3,
                                         uint32_t a0, uint32_t a1, uint32_t a2, uint32_t a3,
                                         uint32_t b0, uint32_t b1) {
    asm volatile(
        "mma.sync.aligned.m16n8k16.row.col.f32.bf16.bf16.f32 "
        "{%0,%1,%2,%3}, {%4,%5,%6,%7}, {%8,%9}, {%0,%1,%2,%3};"
        : "+f"(c0), "+f"(c1), "+f"(c2), "+f"(c3)
        : "r"(a0), "r"(a1), "r"(a2), "r"(a3), "r"(b0), "r"(b1));
}

__global__ void __launch_bounds__(256) gemm_kernel(
    const float* __restrict__ bias, float* __restrict__ C)
{
    extern __shared__ __align__(1024) char smem[];
    uint32_t sb;
    asm("{ .reg .u64 t; cvta.to.shared.u64 t, %1; cvt.u32.u64 %0, t; }"
        : "=r"(sb) : "l"(smem));

    const int tid = threadIdx.x, wid = tid >> 5, lane = tid & 31;
    const int mBase = blockIdx.y * BM, nBase = blockIdx.x * BN;
    const int wm = wid >> 2;          // 0..1 -> M offset wm*64
    const int wn = wid & 3;           // 0..3 -> N offset wn*32

    // ---- cp.async loader for one k-block into stage s ----
    auto load_stage = [&](int kb) {
        const int s = kb % STAGES;
        const int k0 = kb * BK;
        const uint32_t aBase = sb + s * STAGE_BYTES;
        const uint32_t bBase = aBase + ASIZE;
        const __nv_bfloat16* Ag = g_xc + (size_t)mBase * KTOT + k0;
        const __nv_bfloat16* Bg = g_qi + (size_t)nBase * ND + (k0 & (ND - 1));
#pragma unroll
        for (int i = 0; i < 4; ++i) {
            int idx = tid + 256 * i;          // 0..1023
            int r = idx >> 3, c = idx & 7;
            uint32_t dstA = aBase + sw128((uint32_t)(r * 128 + c * 16));
            const void* srcA = Ag + (size_t)r * KTOT + c * 8;
            asm volatile("cp.async.cg.shared.global [%0], [%1], 16;" :: "r"(dstA), "l"(srcA));
            uint32_t dstB = bBase + sw128((uint32_t)(r * 128 + c * 16));
            const void* srcB = Bg + (size_t)r * ND + c * 8;
            asm volatile("cp.async.cg.shared.global [%0], [%1], 16;" :: "r"(dstB), "l"(srcB));
        }
    };

    float acc[4][4][4];
#pragma unroll
    for (int i = 0; i < 4; ++i)
#pragma unroll
        for (int j = 0; j < 4; ++j)
#pragma unroll
            for (int k = 0; k < 4; ++k) acc[i][j][k] = 0.f;

    // prologue: stages 0,1
    load_stage(0);
    asm volatile("cp.async.commit_group;");
    load_stage(1);
    asm volatile("cp.async.commit_group;");

    // precomputed per-thread ldmatrix role offsets
    const int aRow = lane & 15;                  // row within 16-tile
    const int aKb  = (lane >> 4) * 16;           // 0 or 16 bytes (k half)
    const int bRow = ((lane >> 4) & 1) * 8 + (lane & 7);  // n within 16
    const int bKb  = ((lane >> 3) & 1) * 16;     // 0 or 16 bytes

    for (int it = 0; it < NIT; ++it) {
        asm volatile("cp.async.wait_group 1;");
        __syncthreads();

        if (it + 2 < NIT) load_stage(it + 2);
        asm volatile("cp.async.commit_group;");

        const int s = it % STAGES;
        const uint32_t aBase = sb + s * STAGE_BYTES;
        const uint32_t bBase = aBase + ASIZE;

#pragma unroll
        for (int ks = 0; ks < 4; ++ks) {        // 4 x k16
            uint32_t af[4][4], bf[2][4];
#pragma unroll
            for (int mt = 0; mt < 4; ++mt) {
                uint32_t addr = aBase + sw128(
                    (uint32_t)((wm * 64 + mt * 16 + aRow) * 128 + ks * 32 + aKb));
                ldsm_x4(af[mt][0], af[mt][1], af[mt][2], af[mt][3], addr);
            }
#pragma unroll
            for (int np = 0; np < 2; ++np) {    // each covers two 8-wide n tiles
                uint32_t addr = bBase + sw128(
                    (uint32_t)((wn * 32 + np * 16 + bRow) * 128 + ks * 32 + bKb));
                ldsm_x4(bf[np][0], bf[np][1], bf[np][2], bf[np][3], addr);
            }
#pragma unroll
            for (int mt = 0; mt < 4; ++mt)
#pragma unroll
                for (int nt = 0; nt < 4; ++nt) {
                    uint32_t b0 = bf[nt >> 1][(nt & 1) * 2 + 0];
                    uint32_t b1 = bf[nt >> 1][(nt & 1) * 2 + 1];
                    mma16816(acc[mt][nt][0], acc[mt][nt][1], acc[mt][nt][2], acc[mt][nt][3],
                             af[mt][0], af[mt][1], af[mt][2], af[mt][3], b0, b1);
                }
        }
        __syncthreads();
    }

    // ---- epilogue: out = acc * cs[n] + bias[n] ----
#pragma unroll
    for (int nt = 0; nt < 4; ++nt) {
        const int col = nBase + wn * 32 + nt * 8 + (lane & 3) * 2;
        const float cs0 = g_cs[col],  cs1 = g_cs[col + 1];
        const float bi0 = bias[col],  bi1 = bias[col + 1];
#pragma unroll
        for (int mt = 0; mt < 4; ++mt) {
            const int row0 = mBase + wm * 64 + mt * 16 + (lane >> 2);
            float2 o0, o1;
            o0.x = acc[mt][nt][0] * cs0 + bi0;
            o0.y = acc[mt][nt][1] * cs1 + bi1;
            o1.x = acc[mt][nt][2] * cs0 + bi0;
            o1.y = acc[mt][nt][3] * cs1 + bi1;
            *(float2*)(C + (size_t)row0 * ND + col)       = o0;
            *(float2*)(C + (size_t)(row0 + 8) * ND + col) = o1;
        }
    }
}

// ---------------------------------------------------------------------------
// launch
// ---------------------------------------------------------------------------
extern "C" void kernel_launch(void* const* d_in, const int* in_sizes, int n_in,
                              void* d_out, int out_size)
{
    const float* x    = (const float*)d_in[0];
    const float* w    = (const float*)d_in[1];
    const float* bias = (const float*)d_in[2];
    float* out = (float*)d_out;

    // adaptive = min(2, max(0.5, 4096/10000)) = 0.5 ; sf = 30
    float adaptive = (float)ND / 10000.0f;
    if (adaptive < 0.5f) adaptive = 0.5f;
    if (adaptive > 2.0f) adaptive = 2.0f;
    const float sf = 60.0f * adaptive;

    cudaFuncSetAttribute(gemm_kernel,
                         cudaFuncAttributeMaxDynamicSharedMemorySize, SMEM_TOTAL);

    quant_kernel<<<ND, 256>>>(w, sf);
    split_kernel<<<((size_t)ND * ND) / (256 * 8), 256>>>(x);
    dim3 grid(ND / BN, ND / BM);
    gemm_kernel<<<grid, 256, SMEM_TOTAL>>>(bias, out);
}